// round 1
// baseline (speedup 1.0000x reference)
#include <cuda_runtime.h>
#include <cuda_bf16.h>
#include <mma.h>
#include <cstdint>

using namespace nvcuda;

// Problem dims (fixed by the reference)
#define BATCH   2048
#define IN_DIM  4096
#define OUT_DIM 4096

// 64MB decoded-weight scratch (tf32-rounded fp32). Static __device__ allocation
// is the sanctioned scratch mechanism (no cudaMalloc allowed).
__device__ float g_W[(size_t)IN_DIM * OUT_DIM];

// ---------------------------------------------------------------------------
// Kernel 1: decode W[i,j] = tf32_round(mean[indices[i,j]])
// ---------------------------------------------------------------------------
__global__ __launch_bounds__(256) void decode_kernel(const int4* __restrict__ idx,
                                                     const float* __restrict__ mean) {
    int t = blockIdx.x * blockDim.x + threadIdx.x;  // one int4 (4 indices) per thread
    int4 v = idx[t];
    float4 w;
    w.x = wmma::__float_to_tf32(__ldg(mean + v.x));
    w.y = wmma::__float_to_tf32(__ldg(mean + v.y));
    w.z = wmma::__float_to_tf32(__ldg(mean + v.z));
    w.w = wmma::__float_to_tf32(__ldg(mean + v.w));
    reinterpret_cast<float4*>(g_W)[t] = w;
}

// ---------------------------------------------------------------------------
// Kernel 2: tf32 GEMM  out[b, n] = sum_k x[b,k] * W[k,n] + bias[n]
// Block tile 128x128, BK=32, 256 threads (8 warps, 2x4), warp tile 64x32,
// wmma m16n16k8 tf32, cp.async double-buffered smem.
// ---------------------------------------------------------------------------
#define BM 128
#define BN 128
#define BK 32
#define LDA_S 36    // A smem row stride (floats), %4==0, 144B %16==0
#define LDB_S 132   // B smem row stride (floats), %4==0, 528B %16==0
#define A_STAGE (BM * LDA_S)   // 4608 floats
#define B_STAGE (BK * LDB_S)   // 4224 floats
#define SMEM_FLOATS (2 * (A_STAGE + B_STAGE))
#define SMEM_BYTES  (SMEM_FLOATS * 4)   // 70656 B

__device__ __forceinline__ void cp_async16(float* smem_dst, const float* gmem_src) {
    uint32_t s = (uint32_t)__cvta_generic_to_shared(smem_dst);
    asm volatile("cp.async.cg.shared.global [%0], [%1], 16;\n" :: "r"(s), "l"(gmem_src));
}
__device__ __forceinline__ void cp_async_commit() {
    asm volatile("cp.async.commit_group;\n" ::);
}
template <int N>
__device__ __forceinline__ void cp_async_wait() {
    asm volatile("cp.async.wait_group %0;\n" :: "n"(N));
}

__global__ __launch_bounds__(256, 2) void gemm_tf32_kernel(
    const float* __restrict__ A,     // [BATCH, IN_DIM]
    const float* __restrict__ bias,  // [OUT_DIM]
    float* __restrict__ out)         // [BATCH, OUT_DIM]
{
    extern __shared__ float smem[];
    float* As[2] = { smem,               smem + A_STAGE };
    float* Bs[2] = { smem + 2 * A_STAGE, smem + 2 * A_STAGE + B_STAGE };

    const int tid  = threadIdx.x;
    const int lane = tid & 31;
    const int warpId = tid >> 5;
    const int wm = warpId >> 2;    // 0..1  (M offset wm*64)
    const int wn = warpId & 3;     // 0..3  (N offset wn*32)

    const int row0 = blockIdx.y * BM;
    const int col0 = blockIdx.x * BN;

    // Per-thread load coordinates (4 float4 each for A and B per stage)
    // A tile: 128 rows x 8 float4;  B tile: 32 rows x 32 float4
    wmma::fragment<wmma::accumulator, 16, 16, 8, float> acc[4][2];
    #pragma unroll
    for (int i = 0; i < 4; i++)
        #pragma unroll
        for (int j = 0; j < 2; j++)
            wmma::fill_fragment(acc[i][j], 0.0f);

    const int KT = IN_DIM / BK;   // 128 k-tiles

    auto load_stage = [&](int kt, int s) {
        const float* Ag = A + (size_t)row0 * IN_DIM + kt * BK;
        const float* Bg = g_W + (size_t)(kt * BK) * OUT_DIM + col0;
        #pragma unroll
        for (int p = 0; p < 4; p++) {
            int f = tid + p * 256;
            int r = f >> 3, c = (f & 7) * 4;
            cp_async16(&As[s][r * LDA_S + c], Ag + (size_t)r * IN_DIM + c);
        }
        #pragma unroll
        for (int p = 0; p < 4; p++) {
            int f = tid + p * 256;
            int r = f >> 5, c = (f & 31) * 4;
            cp_async16(&Bs[s][r * LDB_S + c], Bg + (size_t)r * OUT_DIM + c);
        }
    };

    // Prologue: stage 0
    load_stage(0, 0);
    cp_async_commit();

    int buf = 0;
    for (int kt = 0; kt < KT; kt++) {
        if (kt + 1 < KT) {
            load_stage(kt + 1, buf ^ 1);
            cp_async_commit();
            cp_async_wait<1>();
        } else {
            cp_async_wait<0>();
        }
        __syncthreads();

        const float* Asb = As[buf];
        const float* Bsb = Bs[buf];
        #pragma unroll
        for (int ks = 0; ks < BK / 8; ks++) {
            wmma::fragment<wmma::matrix_a, 16, 16, 8, wmma::precision::tf32, wmma::row_major> a[4];
            #pragma unroll
            for (int i = 0; i < 4; i++) {
                wmma::load_matrix_sync(a[i], Asb + (wm * 64 + i * 16) * LDA_S + ks * 8, LDA_S);
                #pragma unroll
                for (int e = 0; e < a[i].num_elements; e++)
                    a[i].x[e] = wmma::__float_to_tf32(a[i].x[e]);
            }
            wmma::fragment<wmma::matrix_b, 16, 16, 8, wmma::precision::tf32, wmma::row_major> b[2];
            #pragma unroll
            for (int j = 0; j < 2; j++) {
                // g_W already tf32-rounded in decode; bits pass through unchanged
                wmma::load_matrix_sync(b[j], Bsb + (ks * 8) * LDB_S + wn * 32 + j * 16, LDB_S);
            }
            #pragma unroll
            for (int i = 0; i < 4; i++)
                #pragma unroll
                for (int j = 0; j < 2; j++)
                    wmma::mma_sync(acc[i][j], a[i], b[j], acc[i][j]);
        }
        __syncthreads();
        buf ^= 1;
    }

    // Epilogue: per-warp 16x20 staging in (now free) smem, fused bias add,
    // vectorized float4 global stores.
    __syncthreads();
    float* stage = smem + warpId * (16 * 20);
    #pragma unroll
    for (int i = 0; i < 4; i++) {
        #pragma unroll
        for (int j = 0; j < 2; j++) {
            wmma::store_matrix_sync(stage, acc[i][j], 20, wmma::mem_row_major);
            __syncwarp();
            int r0 = row0 + wm * 64 + i * 16;
            int c0 = col0 + wn * 32 + j * 16;
            #pragma unroll
            for (int e = 0; e < 2; e++) {
                int pos = lane * 4 + e * 128;        // 0..255
                int r = pos >> 4, c = pos & 15;       // c multiple of 4
                float4 v = *reinterpret_cast<const float4*>(stage + r * 20 + c);
                float4 bb = *reinterpret_cast<const float4*>(bias + c0 + c);
                v.x += bb.x; v.y += bb.y; v.z += bb.z; v.w += bb.w;
                *reinterpret_cast<float4*>(out + (size_t)(r0 + r) * OUT_DIM + c0 + c) = v;
            }
            __syncwarp();
        }
    }
}

// ---------------------------------------------------------------------------
// Launch
// ---------------------------------------------------------------------------
extern "C" void kernel_launch(void* const* d_in, const int* in_sizes, int n_in,
                              void* d_out, int out_size) {
    const float* x    = (const float*)d_in[0];  // [2048, 4096] fp32
    const int*   idx  = (const int*)  d_in[1];  // [4096, 4096] int32
    const float* mean = (const float*)d_in[2];  // [4096] fp32
    const float* bias = (const float*)d_in[3];  // [4096] fp32
    float* out = (float*)d_out;                 // [2048, 4096] fp32

    // Kernel 1: decode weights (16M elems, 4 per thread)
    decode_kernel<<<(IN_DIM * OUT_DIM) / (256 * 4), 256>>>(
        (const int4*)idx, mean);

    // Kernel 2: GEMM + bias
    cudaFuncSetAttribute(gemm_tf32_kernel,
                         cudaFuncAttributeMaxDynamicSharedMemorySize, SMEM_BYTES);
    dim3 grid(OUT_DIM / BN, BATCH / BM);   // (32, 16)
    gemm_tf32_kernel<<<grid, 256, SMEM_BYTES>>>(x, bias, out);
}

// round 3
// speedup vs baseline: 3.8675x; 3.8675x over previous
#include <cuda_runtime.h>
#include <cuda_fp16.h>
#include <mma.h>
#include <cstdint>

using namespace nvcuda;

// ---------------------------------------------------------------------------
// Problem dims
// ---------------------------------------------------------------------------
#define BATCH   2048
#define IN_DIM  4096   // K
#define OUT_DIM 4096   // N

// Scratch (static __device__ = sanctioned mechanism).
// g_W_h: decoded weights, [K, N] row-major fp16 (32MB)
// g_A_h: fp16 copy of x, [M, K] row-major (16MB)
__device__ __align__(256) __half g_W_h[(size_t)IN_DIM * OUT_DIM];
__device__ __align__(256) __half g_A_h[(size_t)BATCH * IN_DIM];

// ---------------------------------------------------------------------------
// Kernel 1: decode.  g_W_h[k*N + n] = (half)mean[idx[k*N + n]]
// Fully coalesced: int4 index load, 8-byte (4 x half) store. No transpose.
// ---------------------------------------------------------------------------
__global__ __launch_bounds__(256) void decode_kernel(const int4* __restrict__ idx,
                                                     const float* __restrict__ mean) {
    int t = blockIdx.x * blockDim.x + threadIdx.x;   // 4 elements per thread
    int4 v = idx[t];
    __half2 lo = __floats2half2_rn(__ldg(mean + v.x), __ldg(mean + v.y));
    __half2 hi = __floats2half2_rn(__ldg(mean + v.z), __ldg(mean + v.w));
    uint2 pack;
    pack.x = *reinterpret_cast<uint32_t*>(&lo);
    pack.y = *reinterpret_cast<uint32_t*>(&hi);
    reinterpret_cast<uint2*>(g_W_h)[t] = pack;
}

// ---------------------------------------------------------------------------
// Kernel 2: convert x to fp16 (8 elems / thread)
// ---------------------------------------------------------------------------
__global__ __launch_bounds__(256) void convert_a_kernel(const float4* __restrict__ x) {
    int t = blockIdx.x * blockDim.x + threadIdx.x;
    float4 v0 = x[2 * t];
    float4 v1 = x[2 * t + 1];
    __half2 h0 = __floats2half2_rn(v0.x, v0.y);
    __half2 h1 = __floats2half2_rn(v0.z, v0.w);
    __half2 h2 = __floats2half2_rn(v1.x, v1.y);
    __half2 h3 = __floats2half2_rn(v1.z, v1.w);
    uint4 pack;
    pack.x = *reinterpret_cast<uint32_t*>(&h0);
    pack.y = *reinterpret_cast<uint32_t*>(&h1);
    pack.z = *reinterpret_cast<uint32_t*>(&h2);
    pack.w = *reinterpret_cast<uint32_t*>(&h3);
    reinterpret_cast<uint4*>(g_A_h)[t] = pack;
}

// ---------------------------------------------------------------------------
// Kernel 3: fp16 GEMM (fp32 accumulate) + bias.
// Block 128x128, BK=32, 256 threads (8 warps, 2x4), warp tile 64x32.
// 4-stage cp.async pipeline, ONE __syncthreads per k-iteration.
// ---------------------------------------------------------------------------
#define BM 128
#define BN 128
#define BK 32
#define KT (IN_DIM / BK)        // 128
#define STAGES 4
#define LDA_S 40                // A smem row stride (halves): 80B, %16==0
#define LDB_S 136               // B smem row stride (halves): 272B, %16==0
#define A_STAGE_H (BM * LDA_S)  // 5120 halves (10240 B)
#define B_STAGE_H (BK * LDB_S)  // 4352 halves (8704 B)
#define STAGE_H   (A_STAGE_H + B_STAGE_H)
#define SMEM_BYTES (STAGES * STAGE_H * 2)   // 75776 B

__device__ __forceinline__ void cp_async16(__half* smem_dst, const __half* gmem_src) {
    uint32_t s = (uint32_t)__cvta_generic_to_shared(smem_dst);
    asm volatile("cp.async.cg.shared.global [%0], [%1], 16;\n" :: "r"(s), "l"(gmem_src));
}
__device__ __forceinline__ void cp_async_commit() {
    asm volatile("cp.async.commit_group;\n" ::);
}
template <int N>
__device__ __forceinline__ void cp_async_wait() {
    asm volatile("cp.async.wait_group %0;\n" :: "n"(N));
}

__global__ __launch_bounds__(256, 2) void gemm_fp16_kernel(
    const float* __restrict__ bias,
    float* __restrict__ out)
{
    extern __shared__ __half smem[];

    const int tid    = threadIdx.x;
    const int lane   = tid & 31;
    const int warpId = tid >> 5;
    const int wm = warpId >> 2;   // 0..1 -> M offset wm*64
    const int wn = warpId & 3;    // 0..3 -> N offset wn*32

    const int row0 = blockIdx.y * BM;
    const int col0 = blockIdx.x * BN;

    wmma::fragment<wmma::accumulator, 16, 16, 16, float> acc[4][2];
    #pragma unroll
    for (int i = 0; i < 4; i++)
        #pragma unroll
        for (int j = 0; j < 2; j++)
            wmma::fill_fragment(acc[i][j], 0.0f);

    // Per-stage smem pointers
    auto As = [&](int s) { return smem + s * STAGE_H; };
    auto Bs = [&](int s) { return smem + s * STAGE_H + A_STAGE_H; };

    // Issue all cp.asyncs for one k-tile into stage s.
    auto load_stage = [&](int kt, int s) {
        const __half* Ag = g_A_h + (size_t)row0 * IN_DIM + kt * BK;
        const __half* Bg = g_W_h + (size_t)(kt * BK) * OUT_DIM + col0;
        __half* as = As(s);
        __half* bs = Bs(s);
        // A: 128 rows x 4 chunks of 8 halves  (512 chunks)
        #pragma unroll
        for (int p = 0; p < 2; p++) {
            int f = tid + p * 256;
            int r = f >> 2, c = (f & 3) * 8;
            cp_async16(&as[r * LDA_S + c], Ag + (size_t)r * IN_DIM + c);
        }
        // B: 32 rows x 16 chunks of 8 halves  (512 chunks)
        #pragma unroll
        for (int p = 0; p < 2; p++) {
            int f = tid + p * 256;
            int r = f >> 4, c = (f & 15) * 8;
            cp_async16(&bs[r * LDB_S + c], Bg + (size_t)r * OUT_DIM + c);
        }
    };

    // Prologue: fill STAGES-1 stages
    #pragma unroll
    for (int s = 0; s < STAGES - 1; s++) {
        load_stage(s, s);
        cp_async_commit();
    }

    for (int kt = 0; kt < KT; kt++) {
        cp_async_wait<STAGES - 2>();   // stage kt resident
        __syncthreads();               // all warps past compute of kt-1

        // Prefetch kt+3 into the slot freed at kt-1
        if (kt + STAGES - 1 < KT) {
            load_stage(kt + STAGES - 1, (kt + STAGES - 1) & (STAGES - 1));
        }
        cp_async_commit();             // keep group count in lockstep

        const __half* Asb = As(kt & (STAGES - 1));
        const __half* Bsb = Bs(kt & (STAGES - 1));
        #pragma unroll
        for (int ks = 0; ks < BK / 16; ks++) {
            wmma::fragment<wmma::matrix_a, 16, 16, 16, __half, wmma::row_major> a[4];
            #pragma unroll
            for (int i = 0; i < 4; i++)
                wmma::load_matrix_sync(a[i], Asb + (wm * 64 + i * 16) * LDA_S + ks * 16, LDA_S);
            wmma::fragment<wmma::matrix_b, 16, 16, 16, __half, wmma::row_major> b[2];
            #pragma unroll
            for (int j = 0; j < 2; j++)
                wmma::load_matrix_sync(b[j], Bsb + (ks * 16) * LDB_S + wn * 32 + j * 16, LDB_S);
            #pragma unroll
            for (int i = 0; i < 4; i++)
                #pragma unroll
                for (int j = 0; j < 2; j++)
                    wmma::mma_sync(acc[i][j], a[i], b[j], acc[i][j]);
        }
    }

    // Epilogue: stage each 16x16 acc tile through smem, add bias, float4 stores.
    __syncthreads();
    float* stage = reinterpret_cast<float*>(smem) + warpId * (16 * 20);
    #pragma unroll
    for (int i = 0; i < 4; i++) {
        #pragma unroll
        for (int j = 0; j < 2; j++) {
            wmma::store_matrix_sync(stage, acc[i][j], 20, wmma::mem_row_major);
            __syncwarp();
            int r0 = row0 + wm * 64 + i * 16;
            int c0 = col0 + wn * 32 + j * 16;
            #pragma unroll
            for (int e = 0; e < 2; e++) {
                int pos = lane * 4 + e * 128;     // 0..255
                int r = pos >> 4, c = pos & 15;
                float4 v = *reinterpret_cast<const float4*>(stage + r * 20 + c);
                float4 bb = *reinterpret_cast<const float4*>(bias + c0 + c);
                v.x += bb.x; v.y += bb.y; v.z += bb.z; v.w += bb.w;
                *reinterpret_cast<float4*>(out + (size_t)(r0 + r) * OUT_DIM + c0 + c) = v;
            }
            __syncwarp();
        }
    }
}

// ---------------------------------------------------------------------------
// Launch
// ---------------------------------------------------------------------------
extern "C" void kernel_launch(void* const* d_in, const int* in_sizes, int n_in,
                              void* d_out, int out_size) {
    const float* x    = (const float*)d_in[0];  // [2048, 4096] fp32
    const int*   idx  = (const int*)  d_in[1];  // [4096, 4096] int32
    const float* mean = (const float*)d_in[2];  // [4096] fp32
    const float* bias = (const float*)d_in[3];  // [4096] fp32
    float* out = (float*)d_out;                 // [2048, 4096] fp32

    // 1) decode weights to fp16 (no transpose)
    decode_kernel<<<(IN_DIM * (size_t)OUT_DIM) / (256 * 4), 256>>>(
        (const int4*)idx, mean);

    // 2) convert x to fp16
    convert_a_kernel<<<(BATCH * IN_DIM) / (256 * 8), 256>>>((const float4*)x);

    // 3) fp16 GEMM + bias
    cudaFuncSetAttribute(gemm_fp16_kernel,
                         cudaFuncAttributeMaxDynamicSharedMemorySize, SMEM_BYTES);
    dim3 grid(OUT_DIM / BN, BATCH / BM);   // (32, 16)
    gemm_fp16_kernel<<<grid, 256, SMEM_BYTES>>>(bias, out);
}

// round 4
// speedup vs baseline: 3.9579x; 1.0234x over previous
#include <cuda_runtime.h>
#include <cuda_fp16.h>
#include <cstdint>

// ---------------------------------------------------------------------------
// Problem dims
// ---------------------------------------------------------------------------
#define BATCH   2048
#define IN_DIM  4096   // K
#define OUT_DIM 4096   // N

// Scratch (static __device__ = sanctioned mechanism).
__device__ __align__(256) __half g_W_h[(size_t)IN_DIM * OUT_DIM];  // [K,N] fp16 (32MB)
__device__ __align__(256) __half g_A_h[(size_t)BATCH * IN_DIM];    // [M,K] fp16 (16MB)

// ---------------------------------------------------------------------------
// Kernel 1: decode via smem-staged mean.  g_W_h[k*N+n] = (half)mean[idx[k*N+n]]
// mean (16KB) is loaded to shared once per block; 16 elems/thread amortizes it.
// ---------------------------------------------------------------------------
__global__ __launch_bounds__(256) void decode_kernel(const int4* __restrict__ idx,
                                                     const float* __restrict__ mean) {
    __shared__ float sm[IN_DIM];
    #pragma unroll
    for (int i = threadIdx.x; i < IN_DIM; i += 256) sm[i] = mean[i];
    __syncthreads();

    const size_t base = (size_t)blockIdx.x * (256 * 4) + threadIdx.x;  // int4 units
    #pragma unroll
    for (int p = 0; p < 4; p++) {
        size_t t = base + (size_t)p * 256;
        int4 v = idx[t];
        __half2 lo = __floats2half2_rn(sm[v.x], sm[v.y]);
        __half2 hi = __floats2half2_rn(sm[v.z], sm[v.w]);
        uint2 pk;
        pk.x = *reinterpret_cast<uint32_t*>(&lo);
        pk.y = *reinterpret_cast<uint32_t*>(&hi);
        reinterpret_cast<uint2*>(g_W_h)[t] = pk;
    }
}

// ---------------------------------------------------------------------------
// Kernel 2: convert x to fp16 (8 elems / thread)
// ---------------------------------------------------------------------------
__global__ __launch_bounds__(256) void convert_a_kernel(const float4* __restrict__ x) {
    int t = blockIdx.x * blockDim.x + threadIdx.x;
    float4 v0 = x[2 * t];
    float4 v1 = x[2 * t + 1];
    __half2 h0 = __floats2half2_rn(v0.x, v0.y);
    __half2 h1 = __floats2half2_rn(v0.z, v0.w);
    __half2 h2 = __floats2half2_rn(v1.x, v1.y);
    __half2 h3 = __floats2half2_rn(v1.z, v1.w);
    uint4 pk;
    pk.x = *reinterpret_cast<uint32_t*>(&h0);
    pk.y = *reinterpret_cast<uint32_t*>(&h1);
    pk.z = *reinterpret_cast<uint32_t*>(&h2);
    pk.w = *reinterpret_cast<uint32_t*>(&h3);
    reinterpret_cast<uint4*>(g_A_h)[t] = pk;
}

// ---------------------------------------------------------------------------
// Kernel 3: fp16 GEMM (fp32 accum) + bias, hand-rolled mma.sync + ldmatrix.
// Block 128x128, 4 warps (2x2), warp tile 64x64. BK=32, 4-stage cp.async.
// ---------------------------------------------------------------------------
#define BM 128
#define BN 128
#define BK 32
#define KT (IN_DIM / BK)        // 128
#define STAGES 4
#define LDA_S 40                // A smem row stride (halves): 80B
#define LDB_S 136               // B smem row stride (halves): 272B
#define A_STAGE_H (BM * LDA_S)  // 5120
#define B_STAGE_H (BK * LDB_S)  // 4352
#define STAGE_H   (A_STAGE_H + B_STAGE_H)
#define SMEM_BYTES (STAGES * STAGE_H * 2)   // 75776 B

__device__ __forceinline__ void cp_async16(__half* smem_dst, const __half* gmem_src) {
    uint32_t s = (uint32_t)__cvta_generic_to_shared(smem_dst);
    asm volatile("cp.async.cg.shared.global [%0], [%1], 16;\n" :: "r"(s), "l"(gmem_src));
}
__device__ __forceinline__ void cp_async_commit() {
    asm volatile("cp.async.commit_group;\n" ::);
}
template <int N>
__device__ __forceinline__ void cp_async_wait() {
    asm volatile("cp.async.wait_group %0;\n" :: "n"(N));
}
__device__ __forceinline__ void ldmatrix_x4(uint32_t* r, const __half* p) {
    uint32_t a = (uint32_t)__cvta_generic_to_shared(p);
    asm volatile("ldmatrix.sync.aligned.m8n8.x4.shared.b16 {%0,%1,%2,%3}, [%4];"
                 : "=r"(r[0]), "=r"(r[1]), "=r"(r[2]), "=r"(r[3]) : "r"(a));
}
__device__ __forceinline__ void ldmatrix_x4_trans(uint32_t* r, const __half* p) {
    uint32_t a = (uint32_t)__cvta_generic_to_shared(p);
    asm volatile("ldmatrix.sync.aligned.m8n8.x4.trans.shared.b16 {%0,%1,%2,%3}, [%4];"
                 : "=r"(r[0]), "=r"(r[1]), "=r"(r[2]), "=r"(r[3]) : "r"(a));
}
__device__ __forceinline__ void mma_16816(float* d, const uint32_t* a, const uint32_t* b) {
    asm volatile(
        "mma.sync.aligned.m16n8k16.row.col.f32.f16.f16.f32 "
        "{%0,%1,%2,%3}, {%4,%5,%6,%7}, {%8,%9}, {%0,%1,%2,%3};"
        : "+f"(d[0]), "+f"(d[1]), "+f"(d[2]), "+f"(d[3])
        : "r"(a[0]), "r"(a[1]), "r"(a[2]), "r"(a[3]), "r"(b[0]), "r"(b[1]));
}

__global__ __launch_bounds__(128) void gemm_fp16_kernel(
    const float* __restrict__ bias,
    float* __restrict__ out)
{
    extern __shared__ __half smem[];

    const int tid  = threadIdx.x;
    const int lane = tid & 31;
    const int warpId = tid >> 5;
    const int wm = warpId >> 1;   // 0..1 -> M offset wm*64
    const int wn = warpId & 1;    // 0..1 -> N offset wn*64

    const int row0 = blockIdx.y * BM;
    const int col0 = blockIdx.x * BN;

    float acc[4][8][4];
    #pragma unroll
    for (int i = 0; i < 4; i++)
        #pragma unroll
        for (int j = 0; j < 8; j++)
            #pragma unroll
            for (int e = 0; e < 4; e++)
                acc[i][j][e] = 0.0f;

    auto As = [&](int s) { return smem + s * STAGE_H; };
    auto Bs = [&](int s) { return smem + s * STAGE_H + A_STAGE_H; };

    auto load_stage = [&](int kt, int s) {
        const __half* Ag = g_A_h + (size_t)row0 * IN_DIM + kt * BK;
        const __half* Bg = g_W_h + (size_t)(kt * BK) * OUT_DIM + col0;
        __half* as = As(s);
        __half* bs = Bs(s);
        // A: 128 rows x 4 chunks of 8 halves = 512 chunks, 4/thread
        #pragma unroll
        for (int p = 0; p < 4; p++) {
            int f = tid + p * 128;
            int r = f >> 2, c = (f & 3) * 8;
            cp_async16(&as[r * LDA_S + c], Ag + (size_t)r * IN_DIM + c);
        }
        // B: 32 rows x 16 chunks of 8 halves = 512 chunks, 4/thread
        #pragma unroll
        for (int p = 0; p < 4; p++) {
            int f = tid + p * 128;
            int r = f >> 4, c = (f & 15) * 8;
            cp_async16(&bs[r * LDB_S + c], Bg + (size_t)r * OUT_DIM + c);
        }
    };

    #pragma unroll
    for (int s = 0; s < STAGES - 1; s++) {
        load_stage(s, s);
        cp_async_commit();
    }

    const int lrow = lane & 15;      // ldmatrix source row within 16
    const int lcol = (lane >> 4) * 8;

    for (int kt = 0; kt < KT; kt++) {
        cp_async_wait<STAGES - 2>();
        __syncthreads();

        if (kt + STAGES - 1 < KT)
            load_stage(kt + STAGES - 1, (kt + STAGES - 1) & (STAGES - 1));
        cp_async_commit();

        const __half* Asb = As(kt & (STAGES - 1));
        const __half* Bsb = Bs(kt & (STAGES - 1));

        #pragma unroll
        for (int ks = 0; ks < BK / 16; ks++) {
            uint32_t afr[4][4];
            #pragma unroll
            for (int mt = 0; mt < 4; mt++)
                ldmatrix_x4(afr[mt],
                    Asb + (wm * 64 + mt * 16 + lrow) * LDA_S + ks * 16 + lcol);
            uint32_t bfr[4][4];
            #pragma unroll
            for (int nt2 = 0; nt2 < 4; nt2++)
                ldmatrix_x4_trans(bfr[nt2],
                    Bsb + (ks * 16 + lrow) * LDB_S + wn * 64 + nt2 * 16 + lcol);
            #pragma unroll
            for (int mt = 0; mt < 4; mt++)
                #pragma unroll
                for (int nt = 0; nt < 8; nt++)
                    mma_16816(acc[mt][nt], afr[mt], &bfr[nt >> 1][(nt & 1) * 2]);
        }
    }

    // Epilogue: direct float2 stores with fused bias.
    // acc regs c0,c1 -> row (lane>>2), cols 2*(lane&3)+{0,1}; c2,c3 -> row+8.
    #pragma unroll
    for (int mt = 0; mt < 4; mt++) {
        const int r = row0 + wm * 64 + mt * 16 + (lane >> 2);
        float* o0 = out + (size_t)r * OUT_DIM;
        float* o1 = out + (size_t)(r + 8) * OUT_DIM;
        #pragma unroll
        for (int nt = 0; nt < 8; nt++) {
            const int c = col0 + wn * 64 + nt * 8 + 2 * (lane & 3);
            float2 bb = *reinterpret_cast<const float2*>(bias + c);
            float2 v0 = { acc[mt][nt][0] + bb.x, acc[mt][nt][1] + bb.y };
            float2 v1 = { acc[mt][nt][2] + bb.x, acc[mt][nt][3] + bb.y };
            *reinterpret_cast<float2*>(o0 + c) = v0;
            *reinterpret_cast<float2*>(o1 + c) = v1;
        }
    }
}

// ---------------------------------------------------------------------------
// Launch
// ---------------------------------------------------------------------------
extern "C" void kernel_launch(void* const* d_in, const int* in_sizes, int n_in,
                              void* d_out, int out_size) {
    const float* x    = (const float*)d_in[0];  // [2048, 4096] fp32
    const int*   idx  = (const int*)  d_in[1];  // [4096, 4096] int32
    const float* mean = (const float*)d_in[2];  // [4096] fp32
    const float* bias = (const float*)d_in[3];  // [4096] fp32
    float* out = (float*)d_out;                 // [2048, 4096] fp32

    // 1) decode weights to fp16 (smem-staged mean, 16 elems/thread)
    decode_kernel<<<(IN_DIM * (size_t)OUT_DIM) / (256 * 16), 256>>>(
        (const int4*)idx, mean);

    // 2) convert x to fp16
    convert_a_kernel<<<(BATCH * IN_DIM) / (256 * 8), 256>>>((const float4*)x);

    // 3) fp16 GEMM + bias (mma.sync + ldmatrix)
    cudaFuncSetAttribute(gemm_fp16_kernel,
                         cudaFuncAttributeMaxDynamicSharedMemorySize, SMEM_BYTES);
    dim3 grid(OUT_DIM / BN, BATCH / BM);   // (32, 16)
    gemm_fp16_kernel<<<grid, 128, SMEM_BYTES>>>(bias, out);
}

// round 5
// speedup vs baseline: 4.2962x; 1.0855x over previous
#include <cuda_runtime.h>
#include <cuda_fp16.h>
#include <cstdint>

// ---------------------------------------------------------------------------
// Problem dims
// ---------------------------------------------------------------------------
#define BATCH   2048
#define IN_DIM  4096   // K
#define OUT_DIM 4096   // N

// Scratch (static __device__ = sanctioned mechanism).
__device__ __align__(256) __half g_W_h[(size_t)IN_DIM * OUT_DIM];  // [K,N] fp16 (32MB)
__device__ __align__(256) __half g_A_h[(size_t)BATCH * IN_DIM];    // [M,K] fp16 (16MB)
__device__ int g_ticket;                                            // persistent-GEMM work counter

// ---------------------------------------------------------------------------
// Kernel 1 (fused prep): blocks [0,4096) decode W, [4096,8192) convert A.
// Independent halves co-schedule -> overlap. Block 8191 also resets ticket.
// ---------------------------------------------------------------------------
#define DEC_BLOCKS 4096
#define CNV_BLOCKS 4096

__global__ __launch_bounds__(256) void prep_kernel(const int4* __restrict__ idx,
                                                   const float* __restrict__ mean,
                                                   const float4* __restrict__ x) {
    const int b = blockIdx.x;
    if (b < DEC_BLOCKS) {
        // ---- decode: 1024 int4 per block (4 per thread), smem-staged mean ----
        __shared__ float sm[IN_DIM];
        #pragma unroll
        for (int i = threadIdx.x; i < IN_DIM; i += 256) sm[i] = mean[i];
        __syncthreads();

        const size_t base = (size_t)b * (256 * 4) + threadIdx.x;  // int4 units
        int4 v[4];
        #pragma unroll
        for (int p = 0; p < 4; p++) v[p] = idx[base + (size_t)p * 256];  // 4 LDG.128 in flight
        #pragma unroll
        for (int p = 0; p < 4; p++) {
            __half2 lo = __floats2half2_rn(sm[v[p].x], sm[v[p].y]);
            __half2 hi = __floats2half2_rn(sm[v[p].z], sm[v[p].w]);
            uint2 pk;
            pk.x = *reinterpret_cast<uint32_t*>(&lo);
            pk.y = *reinterpret_cast<uint32_t*>(&hi);
            reinterpret_cast<uint2*>(g_W_h)[base + (size_t)p * 256] = pk;
        }
    } else {
        // ---- convert x to fp16: 8 floats per thread ----
        if (b == DEC_BLOCKS && threadIdx.x == 0) g_ticket = 0;  // reset before GEMM launch
        int t = (b - DEC_BLOCKS) * 256 + threadIdx.x;
        float4 v0 = x[2 * t];
        float4 v1 = x[2 * t + 1];
        __half2 h0 = __floats2half2_rn(v0.x, v0.y);
        __half2 h1 = __floats2half2_rn(v0.z, v0.w);
        __half2 h2 = __floats2half2_rn(v1.x, v1.y);
        __half2 h3 = __floats2half2_rn(v1.z, v1.w);
        uint4 pk;
        pk.x = *reinterpret_cast<uint32_t*>(&h0);
        pk.y = *reinterpret_cast<uint32_t*>(&h1);
        pk.z = *reinterpret_cast<uint32_t*>(&h2);
        pk.w = *reinterpret_cast<uint32_t*>(&h3);
        reinterpret_cast<uint4*>(g_A_h)[t] = pk;
    }
}

// ---------------------------------------------------------------------------
// Kernel 2: persistent fp16 GEMM (fp32 accum) + bias. mma.sync + ldmatrix.
// Block tile 128x128, 4 warps (2x2), warp tile 64x64, BK=32, 4-stage cp.async.
// 296 persistent CTAs (2/SM) pull tiles from a global ticket; next tile's
// prologue is issued before the current epilogue to hide load latency.
// ---------------------------------------------------------------------------
#define BM 128
#define BN 128
#define BK 32
#define KT (IN_DIM / BK)        // 128
#define NTILES ((BATCH / BM) * (OUT_DIM / BN))   // 512
#define NWORKERS 296
#define STAGES 4
#define LDA_S 40                // A smem row stride (halves): 80B
#define LDB_S 136               // B smem row stride (halves): 272B
#define A_STAGE_H (BM * LDA_S)  // 5120
#define B_STAGE_H (BK * LDB_S)  // 4352
#define STAGE_H   (A_STAGE_H + B_STAGE_H)
#define SMEM_BYTES (STAGES * STAGE_H * 2)   // 75776 B (2 CTAs/SM fit: 151KB < 228KB)

__device__ __forceinline__ void cp_async16(__half* smem_dst, const __half* gmem_src) {
    uint32_t s = (uint32_t)__cvta_generic_to_shared(smem_dst);
    asm volatile("cp.async.cg.shared.global [%0], [%1], 16;\n" :: "r"(s), "l"(gmem_src));
}
__device__ __forceinline__ void cp_async_commit() {
    asm volatile("cp.async.commit_group;\n" ::);
}
template <int N>
__device__ __forceinline__ void cp_async_wait() {
    asm volatile("cp.async.wait_group %0;\n" :: "n"(N));
}
__device__ __forceinline__ void ldmatrix_x4(uint32_t* r, const __half* p) {
    uint32_t a = (uint32_t)__cvta_generic_to_shared(p);
    asm volatile("ldmatrix.sync.aligned.m8n8.x4.shared.b16 {%0,%1,%2,%3}, [%4];"
                 : "=r"(r[0]), "=r"(r[1]), "=r"(r[2]), "=r"(r[3]) : "r"(a));
}
__device__ __forceinline__ void ldmatrix_x4_trans(uint32_t* r, const __half* p) {
    uint32_t a = (uint32_t)__cvta_generic_to_shared(p);
    asm volatile("ldmatrix.sync.aligned.m8n8.x4.trans.shared.b16 {%0,%1,%2,%3}, [%4];"
                 : "=r"(r[0]), "=r"(r[1]), "=r"(r[2]), "=r"(r[3]) : "r"(a));
}
__device__ __forceinline__ void mma_16816(float* d, const uint32_t* a, const uint32_t* b) {
    asm volatile(
        "mma.sync.aligned.m16n8k16.row.col.f32.f16.f16.f32 "
        "{%0,%1,%2,%3}, {%4,%5,%6,%7}, {%8,%9}, {%0,%1,%2,%3};"
        : "+f"(d[0]), "+f"(d[1]), "+f"(d[2]), "+f"(d[3])
        : "r"(a[0]), "r"(a[1]), "r"(a[2]), "r"(a[3]), "r"(b[0]), "r"(b[1]));
}

__global__ __launch_bounds__(128) void gemm_fp16_kernel(
    const float* __restrict__ bias,
    float* __restrict__ out)
{
    extern __shared__ __half smem[];
    __shared__ int s_tile;

    const int tid  = threadIdx.x;
    const int lane = tid & 31;
    const int warpId = tid >> 5;
    const int wm = warpId >> 1;   // M offset wm*64
    const int wn = warpId & 1;    // N offset wn*64
    const int lrow = lane & 15;
    const int lcol = (lane >> 4) * 8;

    auto As = [&](int s) { return smem + s * STAGE_H; };
    auto Bs = [&](int s) { return smem + s * STAGE_H + A_STAGE_H; };

    auto load_stage = [&](int kt, int s, int row0, int col0) {
        const __half* Ag = g_A_h + (size_t)row0 * IN_DIM + kt * BK;
        const __half* Bg = g_W_h + (size_t)(kt * BK) * OUT_DIM + col0;
        __half* as = As(s);
        __half* bs = Bs(s);
        #pragma unroll
        for (int p = 0; p < 4; p++) {
            int f = tid + p * 128;
            int r = f >> 2, c = (f & 3) * 8;
            cp_async16(&as[r * LDA_S + c], Ag + (size_t)r * IN_DIM + c);
        }
        #pragma unroll
        for (int p = 0; p < 4; p++) {
            int f = tid + p * 128;
            int r = f >> 4, c = (f & 15) * 8;
            cp_async16(&bs[r * LDB_S + c], Bg + (size_t)r * OUT_DIM + c);
        }
    };

    auto fetch_ticket = [&]() -> int {
        __syncthreads();                       // everyone done with prior s_tile
        if (tid == 0) s_tile = atomicAdd(&g_ticket, 1);
        __syncthreads();
        return s_tile;
    };

    int t = fetch_ticket();
    if (t >= NTILES) return;
    int row0 = (t >> 5) * BM;
    int col0 = (t & 31) * BN;

    // Prologue for first tile
    #pragma unroll
    for (int s = 0; s < STAGES - 1; s++) {
        load_stage(s, s, row0, col0);
        cp_async_commit();
    }

    while (true) {
        float acc[4][8][4];
        #pragma unroll
        for (int i = 0; i < 4; i++)
            #pragma unroll
            for (int j = 0; j < 8; j++)
                #pragma unroll
                for (int e = 0; e < 4; e++)
                    acc[i][j][e] = 0.0f;

        for (int kt = 0; kt < KT; kt++) {
            cp_async_wait<STAGES - 2>();
            __syncthreads();

            if (kt + STAGES - 1 < KT) {
                load_stage(kt + STAGES - 1, (kt + STAGES - 1) & (STAGES - 1), row0, col0);
                cp_async_commit();
            }

            const __half* Asb = As(kt & (STAGES - 1));
            const __half* Bsb = Bs(kt & (STAGES - 1));

            #pragma unroll
            for (int ks = 0; ks < BK / 16; ks++) {
                uint32_t afr[4][4];
                #pragma unroll
                for (int mt = 0; mt < 4; mt++)
                    ldmatrix_x4(afr[mt],
                        Asb + (wm * 64 + mt * 16 + lrow) * LDA_S + ks * 16 + lcol);
                uint32_t bfr[4][4];
                #pragma unroll
                for (int nt2 = 0; nt2 < 4; nt2++)
                    ldmatrix_x4_trans(bfr[nt2],
                        Bsb + (ks * 16 + lrow) * LDB_S + wn * 64 + nt2 * 16 + lcol);
                #pragma unroll
                for (int mt = 0; mt < 4; mt++)
                    #pragma unroll
                    for (int nt = 0; nt < 8; nt++)
                        mma_16816(acc[mt][nt], afr[mt], &bfr[nt >> 1][(nt & 1) * 2]);
            }
        }
        cp_async_wait<0>();   // drain before smem reuse

        // Grab next tile and start its prologue BEFORE the epilogue, so the
        // loads run under the output stores.
        const int erow0 = row0, ecol0 = col0;
        int t2 = fetch_ticket();     // includes the syncthreads that protects smem
        const bool more = (t2 < NTILES);
        if (more) {
            row0 = (t2 >> 5) * BM;
            col0 = (t2 & 31) * BN;
            #pragma unroll
            for (int s = 0; s < STAGES - 1; s++) {
                load_stage(s, s, row0, col0);
                cp_async_commit();
            }
        }

        // Epilogue: direct float2 stores with fused bias.
        #pragma unroll
        for (int mt = 0; mt < 4; mt++) {
            const int r = erow0 + wm * 64 + mt * 16 + (lane >> 2);
            float* o0 = out + (size_t)r * OUT_DIM;
            float* o1 = out + (size_t)(r + 8) * OUT_DIM;
            #pragma unroll
            for (int nt = 0; nt < 8; nt++) {
                const int c = ecol0 + wn * 64 + nt * 8 + 2 * (lane & 3);
                float2 bb = *reinterpret_cast<const float2*>(bias + c);
                float2 v0 = { acc[mt][nt][0] + bb.x, acc[mt][nt][1] + bb.y };
                float2 v1 = { acc[mt][nt][2] + bb.x, acc[mt][nt][3] + bb.y };
                *reinterpret_cast<float2*>(o0 + c) = v0;
                *reinterpret_cast<float2*>(o1 + c) = v1;
            }
        }

        if (!more) break;
    }
}

// ---------------------------------------------------------------------------
// Launch
// ---------------------------------------------------------------------------
extern "C" void kernel_launch(void* const* d_in, const int* in_sizes, int n_in,
                              void* d_out, int out_size) {
    const float* x    = (const float*)d_in[0];  // [2048, 4096] fp32
    const int*   idx  = (const int*)  d_in[1];  // [4096, 4096] int32
    const float* mean = (const float*)d_in[2];  // [4096] fp32
    const float* bias = (const float*)d_in[3];  // [4096] fp32
    float* out = (float*)d_out;                 // [2048, 4096] fp32

    // 1) fused prep: decode W (blocks 0..4095) || convert A (4096..8191); resets ticket
    prep_kernel<<<DEC_BLOCKS + CNV_BLOCKS, 256>>>(
        (const int4*)idx, mean, (const float4*)x);

    // 2) persistent fp16 GEMM + bias
    cudaFuncSetAttribute(gemm_fp16_kernel,
                         cudaFuncAttributeMaxDynamicSharedMemorySize, SMEM_BYTES);
    gemm_fp16_kernel<<<NWORKERS, 128, SMEM_BYTES>>>(bias, out);
}